// round 14
// baseline (speedup 1.0000x reference)
#include <cuda_runtime.h>
#include <cuda_bf16.h>
#include <cstdint>

#define NMAX 100352
#define EMAX 800000
#define CAP  64        // bucket slots per (node, dir)

// ---- scratch (static device globals; no allocation) ----
__device__ float4 g_agg_in[NMAX * 32];
__device__ float4 g_agg_out[NMAX * 32];
__device__ int    g_cnt_in[NMAX], g_cnt_out[NMAX];
__device__ int    g_bkt_in[NMAX * CAP], g_bkt_out[NMAX * CAP];
__device__ int    g_ovf_node[2 * EMAX];   // node | (dir<<30)
__device__ int    g_ovf_nb[2 * EMAX];
__device__ int    g_novf;
__device__ int    g_idx64;
__device__ __nv_bfloat16 g_Wbf[24 * 4096];

// =============================== helpers ===================================
__device__ __forceinline__ uint32_t smem_u32(const void* p) {
    uint32_t a;
    asm("{ .reg .u64 t; cvta.to.shared.u64 t, %1; cvt.u32.u64 %0, t; }" : "=r"(a) : "l"(p));
    return a;
}
__device__ __forceinline__ void cp_async16(uint32_t saddr, const void* g) {
    asm volatile("cp.async.cg.shared.global [%0], [%1], 16;"
                 :: "r"(saddr), "l"(g) : "memory");
}
__device__ __forceinline__ void cp_commit() {
    asm volatile("cp.async.commit_group;" ::: "memory");
}
__device__ __forceinline__ void cp_wait0() {
    asm volatile("cp.async.wait_group 0;" ::: "memory");
}
__device__ __forceinline__ void red_add_f4(float4* p, float4 v) {
    asm volatile("red.global.add.v4.f32 [%0], {%1,%2,%3,%4};"
                 :: "l"(p), "f"(v.x), "f"(v.y), "f"(v.z), "f"(v.w) : "memory");
}
__device__ __forceinline__ uint32_t pack_hi2(float a, float b, float& la, float& lb) {
    __nv_bfloat16 ha = __float2bfloat16_rn(a);
    __nv_bfloat16 hb = __float2bfloat16_rn(b);
    la = a - __bfloat162float(ha);
    lb = b - __bfloat162float(hb);
    __nv_bfloat162 p = __halves2bfloat162(ha, hb);
    return *(uint32_t*)&p;
}
__device__ __forceinline__ uint32_t pack_bf2(float a, float b) {
    __nv_bfloat162 p = __floats2bfloat162_rn(a, b);
    return *(uint32_t*)&p;
}
__device__ __forceinline__ void ldm_x4(uint32_t addr, uint32_t& r0, uint32_t& r1,
                                       uint32_t& r2, uint32_t& r3) {
    asm volatile("ldmatrix.sync.aligned.m8n8.x4.shared.b16 {%0,%1,%2,%3}, [%4];"
                 : "=r"(r0), "=r"(r1), "=r"(r2), "=r"(r3) : "r"(addr));
}
__device__ __forceinline__ void ldm_x2(uint32_t addr, uint32_t& r0, uint32_t& r1) {
    asm volatile("ldmatrix.sync.aligned.m8n8.x2.shared.b16 {%0,%1}, [%2];"
                 : "=r"(r0), "=r"(r1) : "r"(addr));
}
__device__ __forceinline__ void mma_bf16(float* c, const uint32_t* a, const uint32_t* b) {
    asm volatile("mma.sync.aligned.m16n8k16.row.col.f32.bf16.bf16.f32 "
                 "{%0,%1,%2,%3}, {%4,%5,%6,%7}, {%8,%9}, {%0,%1,%2,%3};"
                 : "+f"(c[0]), "+f"(c[1]), "+f"(c[2]), "+f"(c[3])
                 : "r"(a[0]), "r"(a[1]), "r"(a[2]), "r"(a[3]), "r"(b[0]), "r"(b[1]));
}

// ============= init: zero counters + probe + weight prefold ================
__global__ void init_kernel(const long long* ei64,
                            const float* __restrict__ Wself,
                            const float* __restrict__ Ws2d,
                            const float* __restrict__ Wd2s,
                            int E, int n) {
    int i = blockIdx.x * blockDim.x + threadIdx.x;
    if (i < n) { g_cnt_in[i] = 0; g_cnt_out[i] = 0; }
    if (i == 0) g_novf = 0;
    if (blockIdx.x == 0 && threadIdx.x < 32) {
        int lane = threadIdx.x;
        int m = E < 64 ? E : 64;
        bool bad = false;
        for (int j = lane; j < m; j += 32) {
            long long v = ei64[j];
            if (v < 0 || v >= (long long)n) bad = true;
        }
        unsigned any = __ballot_sync(0xFFFFFFFFu, bad);
        if (lane == 0) g_idx64 = (any == 0) ? 1 : 0;
    }
    if (i < 24 * 2048) {
        int c   = i >> 11;
        int rem = i & 2047;
        int nc  = rem >> 4;
        int k   = rem & 15;
        int kglob  = c * 16 + k;
        int seg    = kglob >> 7;
        int klocal = kglob & 127;
        const float* W = seg == 0 ? Wself : (seg == 1 ? Ws2d : Wd2s);
        float coef = seg == 0 ? 1.0f : 0.5f;
        float w = W[klocal * 128 + nc] * coef;
        __nv_bfloat16 hi = __float2bfloat16_rn(w);
        float lo = w - __bfloat162float(hi);
        g_Wbf[c * 4096 + nc * 16 + k]        = hi;
        g_Wbf[c * 4096 + 2048 + nc * 16 + k] = __float2bfloat16_rn(lo);
    }
}

// ==================== direct bucket fill (no scan needed) ==================
__global__ void fill_kernel(const void* __restrict__ ei_raw, int E) {
    int e = blockIdx.x * blockDim.x + threadIdx.x;
    if (e >= E) return;
    int s, d;
    if (g_idx64) {
        const long long* ei = (const long long*)ei_raw;
        s = (int)ei[e]; d = (int)ei[E + e];
    } else {
        const int* ei = (const int*)ei_raw;
        s = ei[e]; d = ei[E + e];
    }
    int p1 = atomicAdd(&g_cnt_in[d], 1);
    if (p1 < CAP) {
        g_bkt_in[d * CAP + p1] = s;
    } else {
        int o = atomicAdd(&g_novf, 1);
        g_ovf_node[o] = d;            // dir 0
        g_ovf_nb[o]   = s;
    }
    int p2 = atomicAdd(&g_cnt_out[s], 1);
    if (p2 < CAP) {
        g_bkt_out[s * CAP + p2] = d;
    } else {
        int o = atomicAdd(&g_novf, 1);
        g_ovf_node[o] = s | (1 << 30);  // dir 1
        g_ovf_nb[o]   = d;
    }
}

// ===== gather-mean: grid-stride, 2 pairs/warp, index+degree prefetch ======
__global__ void gather_kernel(const float4* __restrict__ x4, int n) {
    const int lane  = threadIdx.x & 31;
    const int total = 2 * n;
    const int wstep = (gridDim.x * blockDim.x) >> 5;
    int wg = (blockIdx.x * blockDim.x + threadIdx.x) >> 5;
    if (wg >= total) return;

    int pnode = wg >> 1, pdir = wg & 1;
    int pf_raw = (pdir ? &g_bkt_out[pnode * CAP] : &g_bkt_in[pnode * CAP])[lane];
    int pf_deg = pdir ? g_cnt_out[pnode] : g_cnt_in[pnode];

    for (; wg < total; wg += wstep) {
        const int node = wg >> 1, dir = wg & 1;
        const int* bkt = dir ? &g_bkt_out[node * CAP] : &g_bkt_in[node * CAP];
        int raw0 = pf_raw;
        int deg  = pf_deg;

        int wg2 = wg + wstep;
        if (wg2 < total) {
            int n2 = wg2 >> 1, d2 = wg2 & 1;
            pf_raw = (d2 ? &g_bkt_out[n2 * CAP] : &g_bkt_in[n2 * CAP])[lane];
            pf_deg = d2 ? g_cnt_out[n2] : g_cnt_in[n2];
        }

        int degc = deg < CAP ? deg : CAP;
        float4 a0 = make_float4(0.f, 0.f, 0.f, 0.f);
        float4 a1 = a0, a2 = a0, a3 = a0;

        for (int base = 0; base < degc; base += 32) {
            int m = degc - base; if (m > 32) m = 32;
            int myid = (base == 0) ? raw0
                                   : ((lane < m) ? bkt[base + lane] : 0);
            int j = 0;
            for (; j + 4 <= m; j += 4) {
                int n0 = __shfl_sync(0xFFFFFFFFu, myid, j);
                int n1 = __shfl_sync(0xFFFFFFFFu, myid, j + 1);
                int n2 = __shfl_sync(0xFFFFFFFFu, myid, j + 2);
                int n3 = __shfl_sync(0xFFFFFFFFu, myid, j + 3);
                float4 v0 = __ldg(&x4[n0 * 32 + lane]);
                float4 v1 = __ldg(&x4[n1 * 32 + lane]);
                float4 v2 = __ldg(&x4[n2 * 32 + lane]);
                float4 v3 = __ldg(&x4[n3 * 32 + lane]);
                a0.x += v0.x; a0.y += v0.y; a0.z += v0.z; a0.w += v0.w;
                a1.x += v1.x; a1.y += v1.y; a1.z += v1.z; a1.w += v1.w;
                a2.x += v2.x; a2.y += v2.y; a2.z += v2.z; a2.w += v2.w;
                a3.x += v3.x; a3.y += v3.y; a3.z += v3.z; a3.w += v3.w;
            }
            for (; j < m; j++) {
                int nb = __shfl_sync(0xFFFFFFFFu, myid, j);
                float4 v = __ldg(&x4[nb * 32 + lane]);
                a0.x += v.x; a0.y += v.y; a0.z += v.z; a0.w += v.w;
            }
        }
        float r = deg > 0 ? 1.f / (float)deg : 0.f;
        float4 s;
        s.x = (a0.x + a1.x + a2.x + a3.x) * r;
        s.y = (a0.y + a1.y + a2.y + a3.y) * r;
        s.z = (a0.z + a1.z + a2.z + a3.z) * r;
        s.w = (a0.w + a1.w + a2.w + a3.w) * r;
        float4* dst = dir ? g_agg_out : g_agg_in;
        dst[node * 32 + lane] = s;
    }
}

// ============ overflow fixup (grid-stride; empty in practice) ==============
__global__ void ovf_kernel(const float4* __restrict__ x4) {
    int novf = g_novf;
    int lane = threadIdx.x & 31;
    int wstep = (gridDim.x * blockDim.x) >> 5;
    for (int wrec = (blockIdx.x * blockDim.x + threadIdx.x) >> 5;
         wrec < novf; wrec += wstep) {
        int rec  = g_ovf_node[wrec];
        int dir  = (rec >> 30) & 1;
        int node = rec & 0x3FFFFFFF;
        int nb   = g_ovf_nb[wrec];
        int deg  = dir ? g_cnt_out[node] : g_cnt_in[node];
        float r  = 1.f / (float)deg;
        float4 v = __ldg(&x4[nb * 32 + lane]);
        v.x *= r; v.y *= r; v.z *= r; v.w *= r;
        float4* dst = dir ? g_agg_out : g_agg_in;
        red_add_f4(&dst[node * 32 + lane], v);
    }
}

// ================ bf16x3 mma.sync GEMM (BM=128,BN=128,BK=32) ===============
// Term-major inner loop: accumulator reuse distance 4 (was 1) to break
// HMMA RAW chains.
#define AOFF(buf, ksub, h) ((uint32_t)((((buf) * 2 + (ksub)) * 2 + (h)) * 6144))
#define BOFF(buf, ksub, h) (49152u + AOFF(buf, ksub, h))
#define GEMM_SMEM (2 * 49152)

__global__ __launch_bounds__(256, 2)
void gemm_kernel(const float4* __restrict__ x4,
                 const float* __restrict__ bself,
                 const float* __restrict__ bs2d,
                 const float* __restrict__ bd2s,
                 float* __restrict__ out, int n) {
    extern __shared__ char sm[];
    const uint32_t sb = smem_u32(sm);
    const int tid  = threadIdx.x;
    const int lane = tid & 31;
    const int wid  = tid >> 5;
    const int row0 = blockIdx.x * 128;
    const int wm = (wid >> 2) * 64;
    const int wn = (wid & 3) * 32;

    float acc[4][4][4];
#pragma unroll
    for (int i = 0; i < 4; i++)
#pragma unroll
        for (int j = 0; j < 4; j++)
#pragma unroll
            for (int q = 0; q < 4; q++) acc[i][j][q] = 0.f;

    const uint32_t arow = (uint32_t)((lane & 15) * 48 + ((lane >> 4) << 4));
    const uint32_t brow = (uint32_t)((lane & 7) * 48 + (((lane >> 3) & 1) << 4));

    const int arw  = tid >> 1;
    const int half = tid & 1;
    float4 pa[4];
    auto loadA = [&](int kc) {
        const int seg = kc >> 2;
        const float4* src = seg == 0 ? x4
                          : (seg == 1 ? (const float4*)g_agg_in
                                      : (const float4*)g_agg_out);
        const int r = row0 + arw;
        const int fb = (kc & 3) * 8 + half * 2;
#pragma unroll
        for (int ks = 0; ks < 2; ks++) {
#pragma unroll
            for (int j = 0; j < 2; j++) {
                pa[ks * 2 + j] = (r < n) ? src[r * 32 + fb + ks * 4 + j]
                                         : make_float4(0.f, 0.f, 0.f, 0.f);
            }
        }
    };
    auto storeA = [&](int buf) {
        const uint32_t doff = (uint32_t)(arw * 48 + half * 16);
#pragma unroll
        for (int ks = 0; ks < 2; ks++) {
            float4 f0 = pa[ks * 2], f1 = pa[ks * 2 + 1];
            float l0, l1, l2, l3, l4, l5, l6, l7;
            uint4 H, L;
            H.x = pack_hi2(f0.x, f0.y, l0, l1);
            H.y = pack_hi2(f0.z, f0.w, l2, l3);
            H.z = pack_hi2(f1.x, f1.y, l4, l5);
            H.w = pack_hi2(f1.z, f1.w, l6, l7);
            L.x = pack_bf2(l0, l1); L.y = pack_bf2(l2, l3);
            L.z = pack_bf2(l4, l5); L.w = pack_bf2(l6, l7);
            *(uint4*)(sm + AOFF(buf, ks, 0) + doff) = H;
            *(uint4*)(sm + AOFF(buf, ks, 1) + doff) = L;
        }
    };
    auto issueB = [&](int kc, int buf) {
#pragma unroll
        for (int i = 0; i < 2; i++) {
            int g = tid + i * 256;
            int ks = g >> 8, r = g & 255;
            int h = r >> 7, nrow = r & 127;
            const __nv_bfloat16* src = &g_Wbf[(2 * kc + ks) * 4096 + h * 2048 + nrow * 16];
            uint32_t dst = sb + BOFF(buf, ks, h) + (uint32_t)(nrow * 48);
            cp_async16(dst, src);
            cp_async16(dst + 16, src + 8);
        }
        cp_commit();
    };

    issueB(0, 0);
    loadA(0);

    for (int kc = 0; kc < 12; kc++) {
        const int buf = kc & 1;
        storeA(buf);
        cp_wait0();
        __syncthreads();
        if (kc < 11) {
            issueB(kc + 1, buf ^ 1);
            loadA(kc + 1);
        }
#pragma unroll
        for (int ks = 0; ks < 2; ks++) {
            uint32_t bh[4][2], bl[4][2];
            const uint32_t bbase = sb + (uint32_t)(wn * 48) + brow;
#pragma unroll
            for (int nt = 0; nt < 4; nt++) {
                uint32_t rb = bbase + (uint32_t)(nt * 8 * 48);
                ldm_x2(rb + BOFF(buf, ks, 0), bh[nt][0], bh[nt][1]);
                ldm_x2(rb + BOFF(buf, ks, 1), bl[nt][0], bl[nt][1]);
            }
            const uint32_t abase = sb + (uint32_t)(wm * 48) + arow;
#pragma unroll
            for (int mt = 0; mt < 4; mt++) {
                uint32_t ah[4], al[4];
                uint32_t ra = abase + (uint32_t)(mt * 16 * 48);
                ldm_x4(ra + AOFF(buf, ks, 0), ah[0], ah[1], ah[2], ah[3]);
                ldm_x4(ra + AOFF(buf, ks, 1), al[0], al[1], al[2], al[3]);
                // term-major: reuse distance 4 per accumulator, order per
                // (mt,nt) preserved (hh -> hl -> lh)
#pragma unroll
                for (int nt = 0; nt < 4; nt++)
                    mma_bf16(acc[mt][nt], ah, bh[nt]);
#pragma unroll
                for (int nt = 0; nt < 4; nt++)
                    mma_bf16(acc[mt][nt], ah, bl[nt]);
#pragma unroll
                for (int nt = 0; nt < 4; nt++)
                    mma_bf16(acc[mt][nt], al, bh[nt]);
            }
        }
    }

    // ---- epilogue: bias + store ----
    const int g  = lane >> 2;
    const int t2 = (lane & 3) * 2;
    float2 bias2[4];
#pragma unroll
    for (int nt = 0; nt < 4; nt++) {
        int c = wn + nt * 8 + t2;
        bias2[nt].x = bself[c]     + 0.5f * (bs2d[c]     + bd2s[c]);
        bias2[nt].y = bself[c + 1] + 0.5f * (bs2d[c + 1] + bd2s[c + 1]);
    }
#pragma unroll
    for (int mt = 0; mt < 4; mt++) {
        int r0 = row0 + wm + mt * 16 + g;
        int r1 = r0 + 8;
#pragma unroll
        for (int nt = 0; nt < 4; nt++) {
            int c = wn + nt * 8 + t2;
            if (r0 < n) {
                float2 v;
                v.x = acc[mt][nt][0] + bias2[nt].x;
                v.y = acc[mt][nt][1] + bias2[nt].y;
                *(float2*)&out[r0 * 128 + c] = v;
            }
            if (r1 < n) {
                float2 v;
                v.x = acc[mt][nt][2] + bias2[nt].x;
                v.y = acc[mt][nt][3] + bias2[nt].y;
                *(float2*)&out[r1 * 128 + c] = v;
            }
        }
    }
}

// ================================ launch ===================================
extern "C" void kernel_launch(void* const* d_in, const int* in_sizes, int n_in,
                              void* d_out, int out_size) {
    const float* x     = (const float*)d_in[0];
    const float* Wself = (const float*)d_in[1];
    const float* bself = (const float*)d_in[2];
    const float* Ws2d  = (const float*)d_in[3];
    const float* bs2d  = (const float*)d_in[4];
    const float* Wd2s  = (const float*)d_in[5];
    const float* bd2s  = (const float*)d_in[6];
    const void*  ei    = d_in[7];

    const int n = in_sizes[0] / 128;
    const int E = in_sizes[7] / 2;

    float* out = (float*)d_out;

    static int inited = 0;
    if (!inited) {
        cudaFuncSetAttribute(gemm_kernel,
                             cudaFuncAttributeMaxDynamicSharedMemorySize, GEMM_SMEM);
        inited = 1;
    }

    init_kernel<<<(n + 255) / 256, 256>>>((const long long*)ei,
                                          Wself, Ws2d, Wd2s, E, n);
    fill_kernel<<<(E + 255) / 256, 256>>>(ei, E);

    int gwarps = (2 * n + 1) / 2;
    gather_kernel<<<(gwarps + 7) / 8, 256>>>((const float4*)x, n);
    ovf_kernel<<<256, 256>>>((const float4*)x);

    int gblocks = (n + 127) / 128;
    gemm_kernel<<<gblocks, 256, GEMM_SMEM>>>((const float4*)x,
                                             bself, bs2d, bd2s, out, n);
}

// round 15
// speedup vs baseline: 1.1587x; 1.1587x over previous
#include <cuda_runtime.h>
#include <cuda_bf16.h>
#include <cstdint>

#define NMAX 100352
#define EMAX 800000
#define CAP  16        // bucket slots per (node, dir); overflow path handles rest

// ---- scratch (static device globals; no allocation) ----
__device__ float4 g_agg_in[NMAX * 32];
__device__ float4 g_agg_out[NMAX * 32];
__device__ int    g_cnt_in[NMAX], g_cnt_out[NMAX];
__device__ int    g_bkt_in[NMAX * CAP], g_bkt_out[NMAX * CAP];
__device__ int    g_ovf_node[2 * EMAX];   // node | (dir<<30)
__device__ int    g_ovf_nb[2 * EMAX];
__device__ int    g_novf;
__device__ int    g_idx64;
__device__ __nv_bfloat16 g_Wbf[24 * 4096];

// =============================== helpers ===================================
__device__ __forceinline__ uint32_t smem_u32(const void* p) {
    uint32_t a;
    asm("{ .reg .u64 t; cvta.to.shared.u64 t, %1; cvt.u32.u64 %0, t; }" : "=r"(a) : "l"(p));
    return a;
}
__device__ __forceinline__ void cp_async16(uint32_t saddr, const void* g) {
    asm volatile("cp.async.cg.shared.global [%0], [%1], 16;"
                 :: "r"(saddr), "l"(g) : "memory");
}
__device__ __forceinline__ void cp_commit() {
    asm volatile("cp.async.commit_group;" ::: "memory");
}
__device__ __forceinline__ void cp_wait0() {
    asm volatile("cp.async.wait_group 0;" ::: "memory");
}
__device__ __forceinline__ void red_add_f4(float4* p, float4 v) {
    asm volatile("red.global.add.v4.f32 [%0], {%1,%2,%3,%4};"
                 :: "l"(p), "f"(v.x), "f"(v.y), "f"(v.z), "f"(v.w) : "memory");
}
__device__ __forceinline__ uint32_t pack_hi2(float a, float b, float& la, float& lb) {
    __nv_bfloat16 ha = __float2bfloat16_rn(a);
    __nv_bfloat16 hb = __float2bfloat16_rn(b);
    la = a - __bfloat162float(ha);
    lb = b - __bfloat162float(hb);
    __nv_bfloat162 p = __halves2bfloat162(ha, hb);
    return *(uint32_t*)&p;
}
__device__ __forceinline__ uint32_t pack_bf2(float a, float b) {
    __nv_bfloat162 p = __floats2bfloat162_rn(a, b);
    return *(uint32_t*)&p;
}
__device__ __forceinline__ void ldm_x4(uint32_t addr, uint32_t& r0, uint32_t& r1,
                                       uint32_t& r2, uint32_t& r3) {
    asm volatile("ldmatrix.sync.aligned.m8n8.x4.shared.b16 {%0,%1,%2,%3}, [%4];"
                 : "=r"(r0), "=r"(r1), "=r"(r2), "=r"(r3) : "r"(addr));
}
__device__ __forceinline__ void ldm_x2(uint32_t addr, uint32_t& r0, uint32_t& r1) {
    asm volatile("ldmatrix.sync.aligned.m8n8.x2.shared.b16 {%0,%1}, [%2];"
                 : "=r"(r0), "=r"(r1) : "r"(addr));
}
__device__ __forceinline__ void mma_bf16(float* c, const uint32_t* a, const uint32_t* b) {
    asm volatile("mma.sync.aligned.m16n8k16.row.col.f32.bf16.bf16.f32 "
                 "{%0,%1,%2,%3}, {%4,%5,%6,%7}, {%8,%9}, {%0,%1,%2,%3};"
                 : "+f"(c[0]), "+f"(c[1]), "+f"(c[2]), "+f"(c[3])
                 : "r"(a[0]), "r"(a[1]), "r"(a[2]), "r"(a[3]), "r"(b[0]), "r"(b[1]));
}

// ============= init: zero counters + probe + weight prefold ================
__global__ void init_kernel(const long long* ei64,
                            const float* __restrict__ Wself,
                            const float* __restrict__ Ws2d,
                            const float* __restrict__ Wd2s,
                            int E, int n) {
    int i = blockIdx.x * blockDim.x + threadIdx.x;
    if (i < n) { g_cnt_in[i] = 0; g_cnt_out[i] = 0; }
    if (i == 0) g_novf = 0;
    if (blockIdx.x == 0 && threadIdx.x < 32) {
        int lane = threadIdx.x;
        int m = E < 64 ? E : 64;
        bool bad = false;
        for (int j = lane; j < m; j += 32) {
            long long v = ei64[j];
            if (v < 0 || v >= (long long)n) bad = true;
        }
        unsigned any = __ballot_sync(0xFFFFFFFFu, bad);
        if (lane == 0) g_idx64 = (any == 0) ? 1 : 0;
    }
    if (i < 24 * 2048) {
        int c   = i >> 11;
        int rem = i & 2047;
        int nc  = rem >> 4;
        int k   = rem & 15;
        int kglob  = c * 16 + k;
        int seg    = kglob >> 7;
        int klocal = kglob & 127;
        const float* W = seg == 0 ? Wself : (seg == 1 ? Ws2d : Wd2s);
        float coef = seg == 0 ? 1.0f : 0.5f;
        float w = W[klocal * 128 + nc] * coef;
        __nv_bfloat16 hi = __float2bfloat16_rn(w);
        float lo = w - __bfloat162float(hi);
        g_Wbf[c * 4096 + nc * 16 + k]        = hi;
        g_Wbf[c * 4096 + 2048 + nc * 16 + k] = __float2bfloat16_rn(lo);
    }
}

// ==================== direct bucket fill (no scan needed) ==================
__global__ void fill_kernel(const void* __restrict__ ei_raw, int E) {
    int e = blockIdx.x * blockDim.x + threadIdx.x;
    if (e >= E) return;
    int s, d;
    if (g_idx64) {
        const long long* ei = (const long long*)ei_raw;
        s = (int)ei[e]; d = (int)ei[E + e];
    } else {
        const int* ei = (const int*)ei_raw;
        s = ei[e]; d = ei[E + e];
    }
    int p1 = atomicAdd(&g_cnt_in[d], 1);
    if (p1 < CAP) {
        g_bkt_in[d * CAP + p1] = s;
    } else {
        int o = atomicAdd(&g_novf, 1);
        g_ovf_node[o] = d;            // dir 0
        g_ovf_nb[o]   = s;
    }
    int p2 = atomicAdd(&g_cnt_out[s], 1);
    if (p2 < CAP) {
        g_bkt_out[s * CAP + p2] = d;
    } else {
        int o = atomicAdd(&g_novf, 1);
        g_ovf_node[o] = s | (1 << 30);  // dir 1
        g_ovf_nb[o]   = d;
    }
}

// ==== gather-mean: grid-stride, 2 pairs/warp, prefetch, CAP<=16, lean regs ==
__global__ __launch_bounds__(256, 5)
void gather_kernel(const float4* __restrict__ x4, int n) {
    const int lane  = threadIdx.x & 31;
    const int total = 2 * n;
    const int wstep = (gridDim.x * blockDim.x) >> 5;
    int wg = (blockIdx.x * blockDim.x + threadIdx.x) >> 5;
    if (wg >= total) return;

    // prefetch first pair's bucket row (CAP ints) + degree
    int pnode = wg >> 1, pdir = wg & 1;
    int pf_raw = 0;
    if (lane < CAP)
        pf_raw = (pdir ? &g_bkt_out[pnode * CAP] : &g_bkt_in[pnode * CAP])[lane];
    int pf_deg = pdir ? g_cnt_out[pnode] : g_cnt_in[pnode];

    for (; wg < total; wg += wstep) {
        const int node = wg >> 1, dir = wg & 1;
        int myid = pf_raw;
        int deg  = pf_deg;

        // prefetch next pair while this pair's gathers fly
        int wg2 = wg + wstep;
        if (wg2 < total) {
            int n2 = wg2 >> 1, d2 = wg2 & 1;
            pf_raw = 0;
            if (lane < CAP)
                pf_raw = (d2 ? &g_bkt_out[n2 * CAP] : &g_bkt_in[n2 * CAP])[lane];
            pf_deg = d2 ? g_cnt_out[n2] : g_cnt_in[n2];
        }

        int degc = deg < CAP ? deg : CAP;   // degc <= 16: single pass
        float4 a0 = make_float4(0.f, 0.f, 0.f, 0.f);
        float4 a1 = a0;

        int j = 0;
        for (; j + 4 <= degc; j += 4) {
            int n0 = __shfl_sync(0xFFFFFFFFu, myid, j);
            int n1 = __shfl_sync(0xFFFFFFFFu, myid, j + 1);
            int n2 = __shfl_sync(0xFFFFFFFFu, myid, j + 2);
            int n3 = __shfl_sync(0xFFFFFFFFu, myid, j + 3);
            float4 v0 = __ldg(&x4[n0 * 32 + lane]);
            float4 v1 = __ldg(&x4[n1 * 32 + lane]);
            float4 v2 = __ldg(&x4[n2 * 32 + lane]);
            float4 v3 = __ldg(&x4[n3 * 32 + lane]);
            a0.x += v0.x; a0.y += v0.y; a0.z += v0.z; a0.w += v0.w;
            a1.x += v1.x; a1.y += v1.y; a1.z += v1.z; a1.w += v1.w;
            a0.x += v2.x; a0.y += v2.y; a0.z += v2.z; a0.w += v2.w;
            a1.x += v3.x; a1.y += v3.y; a1.z += v3.z; a1.w += v3.w;
        }
        for (; j < degc; j++) {
            int nb = __shfl_sync(0xFFFFFFFFu, myid, j);
            float4 v = __ldg(&x4[nb * 32 + lane]);
            a0.x += v.x; a0.y += v.y; a0.z += v.z; a0.w += v.w;
        }

        float r = deg > 0 ? 1.f / (float)deg : 0.f;
        float4 s;
        s.x = (a0.x + a1.x) * r;
        s.y = (a0.y + a1.y) * r;
        s.z = (a0.z + a1.z) * r;
        s.w = (a0.w + a1.w) * r;
        float4* dst = dir ? g_agg_out : g_agg_in;
        dst[node * 32 + lane] = s;
    }
}

// ============ overflow fixup (grid-stride; ~1k records at CAP=16) ==========
__global__ void ovf_kernel(const float4* __restrict__ x4) {
    int novf = g_novf;
    int lane = threadIdx.x & 31;
    int wstep = (gridDim.x * blockDim.x) >> 5;
    for (int wrec = (blockIdx.x * blockDim.x + threadIdx.x) >> 5;
         wrec < novf; wrec += wstep) {
        int rec  = g_ovf_node[wrec];
        int dir  = (rec >> 30) & 1;
        int node = rec & 0x3FFFFFFF;
        int nb   = g_ovf_nb[wrec];
        int deg  = dir ? g_cnt_out[node] : g_cnt_in[node];
        float r  = 1.f / (float)deg;
        float4 v = __ldg(&x4[nb * 32 + lane]);
        v.x *= r; v.y *= r; v.z *= r; v.w *= r;
        float4* dst = dir ? g_agg_out : g_agg_in;
        red_add_f4(&dst[node * 32 + lane], v);
    }
}

// ================ bf16x3 mma.sync GEMM (BM=128,BN=128,BK=32) ===============
#define AOFF(buf, ksub, h) ((uint32_t)((((buf) * 2 + (ksub)) * 2 + (h)) * 6144))
#define BOFF(buf, ksub, h) (49152u + AOFF(buf, ksub, h))
#define GEMM_SMEM (2 * 49152)

__global__ __launch_bounds__(256, 2)
void gemm_kernel(const float4* __restrict__ x4,
                 const float* __restrict__ bself,
                 const float* __restrict__ bs2d,
                 const float* __restrict__ bd2s,
                 float* __restrict__ out, int n) {
    extern __shared__ char sm[];
    const uint32_t sb = smem_u32(sm);
    const int tid  = threadIdx.x;
    const int lane = tid & 31;
    const int wid  = tid >> 5;
    const int row0 = blockIdx.x * 128;
    const int wm = (wid >> 2) * 64;
    const int wn = (wid & 3) * 32;

    float acc[4][4][4];
#pragma unroll
    for (int i = 0; i < 4; i++)
#pragma unroll
        for (int j = 0; j < 4; j++)
#pragma unroll
            for (int q = 0; q < 4; q++) acc[i][j][q] = 0.f;

    const uint32_t arow = (uint32_t)((lane & 15) * 48 + ((lane >> 4) << 4));
    const uint32_t brow = (uint32_t)((lane & 7) * 48 + (((lane >> 3) & 1) << 4));

    const int arw  = tid >> 1;
    const int half = tid & 1;
    float4 pa[4];
    auto loadA = [&](int kc) {
        const int seg = kc >> 2;
        const float4* src = seg == 0 ? x4
                          : (seg == 1 ? (const float4*)g_agg_in
                                      : (const float4*)g_agg_out);
        const int r = row0 + arw;
        const int fb = (kc & 3) * 8 + half * 2;
#pragma unroll
        for (int ks = 0; ks < 2; ks++) {
#pragma unroll
            for (int j = 0; j < 2; j++) {
                pa[ks * 2 + j] = (r < n) ? src[r * 32 + fb + ks * 4 + j]
                                         : make_float4(0.f, 0.f, 0.f, 0.f);
            }
        }
    };
    auto storeA = [&](int buf) {
        const uint32_t doff = (uint32_t)(arw * 48 + half * 16);
#pragma unroll
        for (int ks = 0; ks < 2; ks++) {
            float4 f0 = pa[ks * 2], f1 = pa[ks * 2 + 1];
            float l0, l1, l2, l3, l4, l5, l6, l7;
            uint4 H, L;
            H.x = pack_hi2(f0.x, f0.y, l0, l1);
            H.y = pack_hi2(f0.z, f0.w, l2, l3);
            H.z = pack_hi2(f1.x, f1.y, l4, l5);
            H.w = pack_hi2(f1.z, f1.w, l6, l7);
            L.x = pack_bf2(l0, l1); L.y = pack_bf2(l2, l3);
            L.z = pack_bf2(l4, l5); L.w = pack_bf2(l6, l7);
            *(uint4*)(sm + AOFF(buf, ks, 0) + doff) = H;
            *(uint4*)(sm + AOFF(buf, ks, 1) + doff) = L;
        }
    };
    auto issueB = [&](int kc, int buf) {
#pragma unroll
        for (int i = 0; i < 2; i++) {
            int g = tid + i * 256;
            int ks = g >> 8, r = g & 255;
            int h = r >> 7, nrow = r & 127;
            const __nv_bfloat16* src = &g_Wbf[(2 * kc + ks) * 4096 + h * 2048 + nrow * 16];
            uint32_t dst = sb + BOFF(buf, ks, h) + (uint32_t)(nrow * 48);
            cp_async16(dst, src);
            cp_async16(dst + 16, src + 8);
        }
        cp_commit();
    };

    issueB(0, 0);
    loadA(0);

    for (int kc = 0; kc < 12; kc++) {
        const int buf = kc & 1;
        storeA(buf);
        cp_wait0();
        __syncthreads();
        if (kc < 11) {
            issueB(kc + 1, buf ^ 1);
            loadA(kc + 1);
        }
#pragma unroll
        for (int ks = 0; ks < 2; ks++) {
            uint32_t bh[4][2], bl[4][2];
            const uint32_t bbase = sb + (uint32_t)(wn * 48) + brow;
#pragma unroll
            for (int nt = 0; nt < 4; nt++) {
                uint32_t rb = bbase + (uint32_t)(nt * 8 * 48);
                ldm_x2(rb + BOFF(buf, ks, 0), bh[nt][0], bh[nt][1]);
                ldm_x2(rb + BOFF(buf, ks, 1), bl[nt][0], bl[nt][1]);
            }
            const uint32_t abase = sb + (uint32_t)(wm * 48) + arow;
#pragma unroll
            for (int mt = 0; mt < 4; mt++) {
                uint32_t ah[4], al[4];
                uint32_t ra = abase + (uint32_t)(mt * 16 * 48);
                ldm_x4(ra + AOFF(buf, ks, 0), ah[0], ah[1], ah[2], ah[3]);
                ldm_x4(ra + AOFF(buf, ks, 1), al[0], al[1], al[2], al[3]);
#pragma unroll
                for (int nt = 0; nt < 4; nt++) {
                    mma_bf16(acc[mt][nt], ah, bh[nt]);
                    mma_bf16(acc[mt][nt], ah, bl[nt]);
                    mma_bf16(acc[mt][nt], al, bh[nt]);
                }
            }
        }
    }

    // ---- epilogue: bias + store ----
    const int g  = lane >> 2;
    const int t2 = (lane & 3) * 2;
    float2 bias2[4];
#pragma unroll
    for (int nt = 0; nt < 4; nt++) {
        int c = wn + nt * 8 + t2;
        bias2[nt].x = bself[c]     + 0.5f * (bs2d[c]     + bd2s[c]);
        bias2[nt].y = bself[c + 1] + 0.5f * (bs2d[c + 1] + bd2s[c + 1]);
    }
#pragma unroll
    for (int mt = 0; mt < 4; mt++) {
        int r0 = row0 + wm + mt * 16 + g;
        int r1 = r0 + 8;
#pragma unroll
        for (int nt = 0; nt < 4; nt++) {
            int c = wn + nt * 8 + t2;
            if (r0 < n) {
                float2 v;
                v.x = acc[mt][nt][0] + bias2[nt].x;
                v.y = acc[mt][nt][1] + bias2[nt].y;
                *(float2*)&out[r0 * 128 + c] = v;
            }
            if (r1 < n) {
                float2 v;
                v.x = acc[mt][nt][2] + bias2[nt].x;
                v.y = acc[mt][nt][3] + bias2[nt].y;
                *(float2*)&out[r1 * 128 + c] = v;
            }
        }
    }
}

// ================================ launch ===================================
extern "C" void kernel_launch(void* const* d_in, const int* in_sizes, int n_in,
                              void* d_out, int out_size) {
    const float* x     = (const float*)d_in[0];
    const float* Wself = (const float*)d_in[1];
    const float* bself = (const float*)d_in[2];
    const float* Ws2d  = (const float*)d_in[3];
    const float* bs2d  = (const float*)d_in[4];
    const float* Wd2s  = (const float*)d_in[5];
    const float* bd2s  = (const float*)d_in[6];
    const void*  ei    = d_in[7];

    const int n = in_sizes[0] / 128;
    const int E = in_sizes[7] / 2;

    float* out = (float*)d_out;

    static int inited = 0;
    if (!inited) {
        cudaFuncSetAttribute(gemm_kernel,
                             cudaFuncAttributeMaxDynamicSharedMemorySize, GEMM_SMEM);
        inited = 1;
    }

    init_kernel<<<(n + 255) / 256, 256>>>((const long long*)ei,
                                          Wself, Ws2d, Wd2s, E, n);
    fill_kernel<<<(E + 255) / 256, 256>>>(ei, E);

    int gwarps = (2 * n + 1) / 2;
    gather_kernel<<<(gwarps + 7) / 8, 256>>>((const float4*)x, n);
    ovf_kernel<<<256, 256>>>((const float4*)x);

    int gblocks = (n + 127) / 128;
    gemm_kernel<<<gblocks, 256, GEMM_SMEM>>>((const float4*)x,
                                             bself, bs2d, bd2s, out, n);
}

// round 16
// speedup vs baseline: 1.3739x; 1.1858x over previous
#include <cuda_runtime.h>
#include <cuda_bf16.h>
#include <cuda_fp16.h>
#include <cstdint>

#define NMAX 100352
#define EMAX 800000
#define CAP  16        // bucket slots per (node, dir); overflow path handles rest

// ---- scratch (static device globals; no allocation) ----
__device__ float4 g_agg_in[NMAX * 32];
__device__ float4 g_agg_out[NMAX * 32];
__device__ int    g_cnt_in[NMAX], g_cnt_out[NMAX];
__device__ int    g_bkt_in[NMAX * CAP], g_bkt_out[NMAX * CAP];
__device__ int    g_ovf_node[2 * EMAX];   // node | (dir<<30)
__device__ int    g_ovf_nb[2 * EMAX];
__device__ int    g_novf;
__device__ int    g_idx64;
__device__ __half g_Wh[24 * 2048];   // fp16 W, coef folded, [c][nc][k16]

// =============================== helpers ===================================
__device__ __forceinline__ uint32_t smem_u32(const void* p) {
    uint32_t a;
    asm("{ .reg .u64 t; cvta.to.shared.u64 t, %1; cvt.u32.u64 %0, t; }" : "=r"(a) : "l"(p));
    return a;
}
__device__ __forceinline__ void cp_async16(uint32_t saddr, const void* g) {
    asm volatile("cp.async.cg.shared.global [%0], [%1], 16;"
                 :: "r"(saddr), "l"(g) : "memory");
}
__device__ __forceinline__ void cp_commit() {
    asm volatile("cp.async.commit_group;" ::: "memory");
}
__device__ __forceinline__ void cp_wait0() {
    asm volatile("cp.async.wait_group 0;" ::: "memory");
}
__device__ __forceinline__ void red_add_f4(float4* p, float4 v) {
    asm volatile("red.global.add.v4.f32 [%0], {%1,%2,%3,%4};"
                 :: "l"(p), "f"(v.x), "f"(v.y), "f"(v.z), "f"(v.w) : "memory");
}
// fp16 split: returns packed half2(hi(a), hi(b)); residuals out in la, lb.
__device__ __forceinline__ uint32_t pack_hi2_f16(float a, float b, float& la, float& lb) {
    __half ha = __float2half_rn(a);
    __half hb = __float2half_rn(b);
    la = a - __half2float(ha);
    lb = b - __half2float(hb);
    __half2 p = __halves2half2(ha, hb);
    return *(uint32_t*)&p;
}
__device__ __forceinline__ uint32_t pack_f16x2(float a, float b) {
    __half2 p = __floats2half2_rn(a, b);
    return *(uint32_t*)&p;
}
__device__ __forceinline__ void ldm_x4(uint32_t addr, uint32_t& r0, uint32_t& r1,
                                       uint32_t& r2, uint32_t& r3) {
    asm volatile("ldmatrix.sync.aligned.m8n8.x4.shared.b16 {%0,%1,%2,%3}, [%4];"
                 : "=r"(r0), "=r"(r1), "=r"(r2), "=r"(r3) : "r"(addr));
}
__device__ __forceinline__ void ldm_x2(uint32_t addr, uint32_t& r0, uint32_t& r1) {
    asm volatile("ldmatrix.sync.aligned.m8n8.x2.shared.b16 {%0,%1}, [%2];"
                 : "=r"(r0), "=r"(r1) : "r"(addr));
}
__device__ __forceinline__ void mma_f16(float* c, const uint32_t* a, const uint32_t* b) {
    asm volatile("mma.sync.aligned.m16n8k16.row.col.f32.f16.f16.f32 "
                 "{%0,%1,%2,%3}, {%4,%5,%6,%7}, {%8,%9}, {%0,%1,%2,%3};"
                 : "+f"(c[0]), "+f"(c[1]), "+f"(c[2]), "+f"(c[3])
                 : "r"(a[0]), "r"(a[1]), "r"(a[2]), "r"(a[3]), "r"(b[0]), "r"(b[1]));
}

// ============= init: zero counters + probe + weight prefold ================
__global__ void init_kernel(const long long* ei64,
                            const float* __restrict__ Wself,
                            const float* __restrict__ Ws2d,
                            const float* __restrict__ Wd2s,
                            int E, int n) {
    int i = blockIdx.x * blockDim.x + threadIdx.x;
    if (i < n) { g_cnt_in[i] = 0; g_cnt_out[i] = 0; }
    if (i == 0) g_novf = 0;
    if (blockIdx.x == 0 && threadIdx.x < 32) {
        int lane = threadIdx.x;
        int m = E < 64 ? E : 64;
        bool bad = false;
        for (int j = lane; j < m; j += 32) {
            long long v = ei64[j];
            if (v < 0 || v >= (long long)n) bad = true;
        }
        unsigned any = __ballot_sync(0xFFFFFFFFu, bad);
        if (lane == 0) g_idx64 = (any == 0) ? 1 : 0;
    }
    if (i < 24 * 2048) {
        int c   = i >> 11;       // chunk 0..23 (2 per 32-k group)
        int rem = i & 2047;
        int nc  = rem >> 4;      // 0..127
        int k   = rem & 15;
        int kglob  = c * 16 + k;
        int seg    = kglob >> 7;
        int klocal = kglob & 127;
        const float* W = seg == 0 ? Wself : (seg == 1 ? Ws2d : Wd2s);
        float coef = seg == 0 ? 1.0f : 0.5f;
        float w = W[klocal * 128 + nc] * coef;
        g_Wh[c * 2048 + nc * 16 + k] = __float2half_rn(w);
    }
}

// ==================== direct bucket fill (no scan needed) ==================
__global__ void fill_kernel(const void* __restrict__ ei_raw, int E) {
    int e = blockIdx.x * blockDim.x + threadIdx.x;
    if (e >= E) return;
    int s, d;
    if (g_idx64) {
        const long long* ei = (const long long*)ei_raw;
        s = (int)ei[e]; d = (int)ei[E + e];
    } else {
        const int* ei = (const int*)ei_raw;
        s = ei[e]; d = ei[E + e];
    }
    int p1 = atomicAdd(&g_cnt_in[d], 1);
    if (p1 < CAP) {
        g_bkt_in[d * CAP + p1] = s;
    } else {
        int o = atomicAdd(&g_novf, 1);
        g_ovf_node[o] = d;            // dir 0
        g_ovf_nb[o]   = s;
    }
    int p2 = atomicAdd(&g_cnt_out[s], 1);
    if (p2 < CAP) {
        g_bkt_out[s * CAP + p2] = d;
    } else {
        int o = atomicAdd(&g_novf, 1);
        g_ovf_node[o] = s | (1 << 30);  // dir 1
        g_ovf_nb[o]   = d;
    }
}

// ==== gather-mean: grid-stride, 2 pairs/warp, prefetch, CAP<=16, lean regs ==
__global__ __launch_bounds__(256, 5)
void gather_kernel(const float4* __restrict__ x4, int n) {
    const int lane  = threadIdx.x & 31;
    const int total = 2 * n;
    const int wstep = (gridDim.x * blockDim.x) >> 5;
    int wg = (blockIdx.x * blockDim.x + threadIdx.x) >> 5;
    if (wg >= total) return;

    int pnode = wg >> 1, pdir = wg & 1;
    int pf_raw = 0;
    if (lane < CAP)
        pf_raw = (pdir ? &g_bkt_out[pnode * CAP] : &g_bkt_in[pnode * CAP])[lane];
    int pf_deg = pdir ? g_cnt_out[pnode] : g_cnt_in[pnode];

    for (; wg < total; wg += wstep) {
        const int node = wg >> 1, dir = wg & 1;
        int myid = pf_raw;
        int deg  = pf_deg;

        int wg2 = wg + wstep;
        if (wg2 < total) {
            int n2 = wg2 >> 1, d2 = wg2 & 1;
            pf_raw = 0;
            if (lane < CAP)
                pf_raw = (d2 ? &g_bkt_out[n2 * CAP] : &g_bkt_in[n2 * CAP])[lane];
            pf_deg = d2 ? g_cnt_out[n2] : g_cnt_in[n2];
        }

        int degc = deg < CAP ? deg : CAP;
        float4 a0 = make_float4(0.f, 0.f, 0.f, 0.f);
        float4 a1 = a0;

        int j = 0;
        for (; j + 4 <= degc; j += 4) {
            int n0 = __shfl_sync(0xFFFFFFFFu, myid, j);
            int n1 = __shfl_sync(0xFFFFFFFFu, myid, j + 1);
            int n2 = __shfl_sync(0xFFFFFFFFu, myid, j + 2);
            int n3 = __shfl_sync(0xFFFFFFFFu, myid, j + 3);
            float4 v0 = __ldg(&x4[n0 * 32 + lane]);
            float4 v1 = __ldg(&x4[n1 * 32 + lane]);
            float4 v2 = __ldg(&x4[n2 * 32 + lane]);
            float4 v3 = __ldg(&x4[n3 * 32 + lane]);
            a0.x += v0.x; a0.y += v0.y; a0.z += v0.z; a0.w += v0.w;
            a1.x += v1.x; a1.y += v1.y; a1.z += v1.z; a1.w += v1.w;
            a0.x += v2.x; a0.y += v2.y; a0.z += v2.z; a0.w += v2.w;
            a1.x += v3.x; a1.y += v3.y; a1.z += v3.z; a1.w += v3.w;
        }
        for (; j < degc; j++) {
            int nb = __shfl_sync(0xFFFFFFFFu, myid, j);
            float4 v = __ldg(&x4[nb * 32 + lane]);
            a0.x += v.x; a0.y += v.y; a0.z += v.z; a0.w += v.w;
        }

        float r = deg > 0 ? 1.f / (float)deg : 0.f;
        float4 s;
        s.x = (a0.x + a1.x) * r;
        s.y = (a0.y + a1.y) * r;
        s.z = (a0.z + a1.z) * r;
        s.w = (a0.w + a1.w) * r;
        float4* dst = dir ? g_agg_out : g_agg_in;
        dst[node * 32 + lane] = s;
    }
}

// ============ overflow fixup (grid-stride; ~1k records at CAP=16) ==========
__global__ void ovf_kernel(const float4* __restrict__ x4) {
    int novf = g_novf;
    int lane = threadIdx.x & 31;
    int wstep = (gridDim.x * blockDim.x) >> 5;
    for (int wrec = (blockIdx.x * blockDim.x + threadIdx.x) >> 5;
         wrec < novf; wrec += wstep) {
        int rec  = g_ovf_node[wrec];
        int dir  = (rec >> 30) & 1;
        int node = rec & 0x3FFFFFFF;
        int nb   = g_ovf_nb[wrec];
        int deg  = dir ? g_cnt_out[node] : g_cnt_in[node];
        float r  = 1.f / (float)deg;
        float4 v = __ldg(&x4[nb * 32 + lane]);
        v.x *= r; v.y *= r; v.z *= r; v.w *= r;
        float4* dst = dir ? g_agg_out : g_agg_in;
        red_add_f4(&dst[node * 32 + lane], v);
    }
}

// ============ fp16 A-split mma.sync GEMM (BM=128,BN=128,BK=32) =============
// 2-term: ah*bh + al*bh. A split into fp16 hi/lo (lo of O(1) features stays
// normal-range); B is fp16-rounded only (its residual is the dropped ~2^-11
// error term). 768 mma/warp vs 1152 for bf16x3.
#define AOFF(buf, ksub, h) ((uint32_t)((((buf) * 2 + (ksub)) * 2 + (h)) * 6144))
#define BOFF(buf, ksub)    (49152u + (uint32_t)(((buf) * 2 + (ksub)) * 6144))
#define GEMM_SMEM (49152 + 4 * 6144)

__global__ __launch_bounds__(256, 2)
void gemm_kernel(const float4* __restrict__ x4,
                 const float* __restrict__ bself,
                 const float* __restrict__ bs2d,
                 const float* __restrict__ bd2s,
                 float* __restrict__ out, int n) {
    extern __shared__ char sm[];
    const uint32_t sb = smem_u32(sm);
    const int tid  = threadIdx.x;
    const int lane = tid & 31;
    const int wid  = tid >> 5;
    const int row0 = blockIdx.x * 128;
    const int wm = (wid >> 2) * 64;
    const int wn = (wid & 3) * 32;

    float acc[4][4][4];
#pragma unroll
    for (int i = 0; i < 4; i++)
#pragma unroll
        for (int j = 0; j < 4; j++)
#pragma unroll
            for (int q = 0; q < 4; q++) acc[i][j][q] = 0.f;

    const uint32_t arow = (uint32_t)((lane & 15) * 48 + ((lane >> 4) << 4));
    const uint32_t brow = (uint32_t)((lane & 7) * 48 + (((lane >> 3) & 1) << 4));

    const int arw  = tid >> 1;
    const int half = tid & 1;
    float4 pa[4];
    auto loadA = [&](int kc) {
        const int seg = kc >> 2;
        const float4* src = seg == 0 ? x4
                          : (seg == 1 ? (const float4*)g_agg_in
                                      : (const float4*)g_agg_out);
        const int r = row0 + arw;
        const int fb = (kc & 3) * 8 + half * 2;
#pragma unroll
        for (int ks = 0; ks < 2; ks++) {
#pragma unroll
            for (int j = 0; j < 2; j++) {
                pa[ks * 2 + j] = (r < n) ? src[r * 32 + fb + ks * 4 + j]
                                         : make_float4(0.f, 0.f, 0.f, 0.f);
            }
        }
    };
    auto storeA = [&](int buf) {
        const uint32_t doff = (uint32_t)(arw * 48 + half * 16);
#pragma unroll
        for (int ks = 0; ks < 2; ks++) {
            float4 f0 = pa[ks * 2], f1 = pa[ks * 2 + 1];
            float l0, l1, l2, l3, l4, l5, l6, l7;
            uint4 H, L;
            H.x = pack_hi2_f16(f0.x, f0.y, l0, l1);
            H.y = pack_hi2_f16(f0.z, f0.w, l2, l3);
            H.z = pack_hi2_f16(f1.x, f1.y, l4, l5);
            H.w = pack_hi2_f16(f1.z, f1.w, l6, l7);
            L.x = pack_f16x2(l0, l1); L.y = pack_f16x2(l2, l3);
            L.z = pack_f16x2(l4, l5); L.w = pack_f16x2(l6, l7);
            *(uint4*)(sm + AOFF(buf, ks, 0) + doff) = H;
            *(uint4*)(sm + AOFF(buf, ks, 1) + doff) = L;
        }
    };
    // B: 2 ksub x 128 rows x 32B (16 fp16), 48B stride. 256 rows -> 1/thread.
    auto issueB = [&](int kc, int buf) {
        int ks = tid >> 7, nrow = tid & 127;
        const __half* src = &g_Wh[(2 * kc + ks) * 2048 + nrow * 16];
        uint32_t dst = sb + BOFF(buf, ks) + (uint32_t)(nrow * 48);
        cp_async16(dst, src);
        cp_async16(dst + 16, src + 8);
        cp_commit();
    };

    issueB(0, 0);
    loadA(0);

    for (int kc = 0; kc < 12; kc++) {
        const int buf = kc & 1;
        storeA(buf);
        cp_wait0();
        __syncthreads();
        if (kc < 11) {
            issueB(kc + 1, buf ^ 1);
            loadA(kc + 1);
        }
#pragma unroll
        for (int ks = 0; ks < 2; ks++) {
            uint32_t bh[4][2];
            const uint32_t bbase = sb + (uint32_t)(wn * 48) + brow;
#pragma unroll
            for (int nt = 0; nt < 4; nt++) {
                uint32_t rb = bbase + (uint32_t)(nt * 8 * 48);
                ldm_x2(rb + BOFF(buf, ks), bh[nt][0], bh[nt][1]);
            }
            const uint32_t abase = sb + (uint32_t)(wm * 48) + arow;
#pragma unroll
            for (int mt = 0; mt < 4; mt++) {
                uint32_t ah[4], al[4];
                uint32_t ra = abase + (uint32_t)(mt * 16 * 48);
                ldm_x4(ra + AOFF(buf, ks, 0), ah[0], ah[1], ah[2], ah[3]);
                ldm_x4(ra + AOFF(buf, ks, 1), al[0], al[1], al[2], al[3]);
#pragma unroll
                for (int nt = 0; nt < 4; nt++) {
                    mma_f16(acc[mt][nt], ah, bh[nt]);
                    mma_f16(acc[mt][nt], al, bh[nt]);
                }
            }
        }
    }

    // ---- epilogue: bias + store ----
    const int g  = lane >> 2;
    const int t2 = (lane & 3) * 2;
    float2 bias2[4];
#pragma unroll
    for (int nt = 0; nt < 4; nt++) {
        int c = wn + nt * 8 + t2;
        bias2[nt].x = bself[c]     + 0.5f * (bs2d[c]     + bd2s[c]);
        bias2[nt].y = bself[c + 1] + 0.5f * (bs2d[c + 1] + bd2s[c + 1]);
    }
#pragma unroll
    for (int mt = 0; mt < 4; mt++) {
        int r0 = row0 + wm + mt * 16 + g;
        int r1 = r0 + 8;
#pragma unroll
        for (int nt = 0; nt < 4; nt++) {
            int c = wn + nt * 8 + t2;
            if (r0 < n) {
                float2 v;
                v.x = acc[mt][nt][0] + bias2[nt].x;
                v.y = acc[mt][nt][1] + bias2[nt].y;
                *(float2*)&out[r0 * 128 + c] = v;
            }
            if (r1 < n) {
                float2 v;
                v.x = acc[mt][nt][2] + bias2[nt].x;
                v.y = acc[mt][nt][3] + bias2[nt].y;
                *(float2*)&out[r1 * 128 + c] = v;
            }
        }
    }
}

// ================================ launch ===================================
extern "C" void kernel_launch(void* const* d_in, const int* in_sizes, int n_in,
                              void* d_out, int out_size) {
    const float* x     = (const float*)d_in[0];
    const float* Wself = (const float*)d_in[1];
    const float* bself = (const float*)d_in[2];
    const float* Ws2d  = (const float*)d_in[3];
    const float* bs2d  = (const float*)d_in[4];
    const float* Wd2s  = (const float*)d_in[5];
    const float* bd2s  = (const float*)d_in[6];
    const void*  ei    = d_in[7];

    const int n = in_sizes[0] / 128;
    const int E = in_sizes[7] / 2;

    float* out = (float*)d_out;

    static int inited = 0;
    if (!inited) {
        cudaFuncSetAttribute(gemm_kernel,
                             cudaFuncAttributeMaxDynamicSharedMemorySize, GEMM_SMEM);
        inited = 1;
    }

    init_kernel<<<(n + 255) / 256, 256>>>((const long long*)ei,
                                          Wself, Ws2d, Wd2s, E, n);
    fill_kernel<<<(E + 255) / 256, 256>>>(ei, E);

    int gwarps = (2 * n + 1) / 2;
    gather_kernel<<<(gwarps + 7) / 8, 256>>>((const float4*)x, n);
    ovf_kernel<<<64, 256>>>((const float4*)x);

    int gblocks = (n + 127) / 128;
    gemm_kernel<<<gblocks, 256, GEMM_SMEM>>>((const float4*)x,
                                             bself, bs2d, bd2s, out, n);
}

// round 17
// speedup vs baseline: 1.3741x; 1.0002x over previous
#include <cuda_runtime.h>
#include <cuda_bf16.h>
#include <cuda_fp16.h>
#include <cstdint>

#define NMAX 100352
#define EMAX 800000
#define CAP  16        // bucket slots per (node, dir); overflow path handles rest

// ---- scratch (static device globals; no allocation) ----
__device__ float4 g_agg_in[NMAX * 32];
__device__ float4 g_agg_out[NMAX * 32];
__device__ int    g_cnt_in[NMAX], g_cnt_out[NMAX];
__device__ int    g_bkt_in[NMAX * CAP], g_bkt_out[NMAX * CAP];
__device__ int    g_ovf_node[2 * EMAX];   // node | (dir<<30)
__device__ int    g_ovf_nb[2 * EMAX];
__device__ int    g_novf;
__device__ int    g_idx64;
__device__ __half g_Wh[24 * 2048];        // fp16 W, coef folded, [c][nc][k16]
__device__ __half g_xh[NMAX * 128];       // fp16 mirror of x (gather source)

// =============================== helpers ===================================
__device__ __forceinline__ uint32_t smem_u32(const void* p) {
    uint32_t a;
    asm("{ .reg .u64 t; cvta.to.shared.u64 t, %1; cvt.u32.u64 %0, t; }" : "=r"(a) : "l"(p));
    return a;
}
__device__ __forceinline__ void cp_async16(uint32_t saddr, const void* g) {
    asm volatile("cp.async.cg.shared.global [%0], [%1], 16;"
                 :: "r"(saddr), "l"(g) : "memory");
}
__device__ __forceinline__ void cp_commit() {
    asm volatile("cp.async.commit_group;" ::: "memory");
}
__device__ __forceinline__ void cp_wait0() {
    asm volatile("cp.async.wait_group 0;" ::: "memory");
}
__device__ __forceinline__ void red_add_f4(float4* p, float4 v) {
    asm volatile("red.global.add.v4.f32 [%0], {%1,%2,%3,%4};"
                 :: "l"(p), "f"(v.x), "f"(v.y), "f"(v.z), "f"(v.w) : "memory");
}
__device__ __forceinline__ uint32_t pack_hi2_f16(float a, float b, float& la, float& lb) {
    __half ha = __float2half_rn(a);
    __half hb = __float2half_rn(b);
    la = a - __half2float(ha);
    lb = b - __half2float(hb);
    __half2 p = __halves2half2(ha, hb);
    return *(uint32_t*)&p;
}
__device__ __forceinline__ uint32_t pack_f16x2(float a, float b) {
    __half2 p = __floats2half2_rn(a, b);
    return *(uint32_t*)&p;
}
__device__ __forceinline__ void ldm_x4(uint32_t addr, uint32_t& r0, uint32_t& r1,
                                       uint32_t& r2, uint32_t& r3) {
    asm volatile("ldmatrix.sync.aligned.m8n8.x4.shared.b16 {%0,%1,%2,%3}, [%4];"
                 : "=r"(r0), "=r"(r1), "=r"(r2), "=r"(r3) : "r"(addr));
}
__device__ __forceinline__ void ldm_x2(uint32_t addr, uint32_t& r0, uint32_t& r1) {
    asm volatile("ldmatrix.sync.aligned.m8n8.x2.shared.b16 {%0,%1}, [%2];"
                 : "=r"(r0), "=r"(r1) : "r"(addr));
}
__device__ __forceinline__ void mma_f16(float* c, const uint32_t* a, const uint32_t* b) {
    asm volatile("mma.sync.aligned.m16n8k16.row.col.f32.f16.f16.f32 "
                 "{%0,%1,%2,%3}, {%4,%5,%6,%7}, {%8,%9}, {%0,%1,%2,%3};"
                 : "+f"(c[0]), "+f"(c[1]), "+f"(c[2]), "+f"(c[3])
                 : "r"(a[0]), "r"(a[1]), "r"(a[2]), "r"(a[3]), "r"(b[0]), "r"(b[1]));
}

// ==== init: zero counters + probe + weight prefold + fp16 mirror of x ======
__global__ void init_kernel(const long long* ei64,
                            const float4* __restrict__ x4,
                            const float* __restrict__ Wself,
                            const float* __restrict__ Ws2d,
                            const float* __restrict__ Wd2s,
                            int E, int n) {
    int i = blockIdx.x * blockDim.x + threadIdx.x;
    int nthreads = gridDim.x * blockDim.x;
    if (i < n) { g_cnt_in[i] = 0; g_cnt_out[i] = 0; }
    if (i == 0) g_novf = 0;
    if (blockIdx.x == 0 && threadIdx.x < 32) {
        int lane = threadIdx.x;
        int m = E < 64 ? E : 64;
        bool bad = false;
        for (int j = lane; j < m; j += 32) {
            long long v = ei64[j];
            if (v < 0 || v >= (long long)n) bad = true;
        }
        unsigned any = __ballot_sync(0xFFFFFFFFu, bad);
        if (lane == 0) g_idx64 = (any == 0) ? 1 : 0;
    }
    if (i < 24 * 2048) {
        int c   = i >> 11;
        int rem = i & 2047;
        int nc  = rem >> 4;
        int k   = rem & 15;
        int kglob  = c * 16 + k;
        int seg    = kglob >> 7;
        int klocal = kglob & 127;
        const float* W = seg == 0 ? Wself : (seg == 1 ? Ws2d : Wd2s);
        float coef = seg == 0 ? 1.0f : 0.5f;
        float w = W[klocal * 128 + nc] * coef;
        g_Wh[c * 2048 + nc * 16 + k] = __float2half_rn(w);
    }
    // fp16 mirror of x: n*32 float4 chunks -> 4 halfs each
    int total4 = n * 32;
    for (int t = i; t < total4; t += nthreads) {
        float4 v = x4[t];
        __half2 h0 = __floats2half2_rn(v.x, v.y);
        __half2 h1 = __floats2half2_rn(v.z, v.w);
        uint2 u;
        u.x = *(uint32_t*)&h0;
        u.y = *(uint32_t*)&h1;
        *(uint2*)&g_xh[t * 4] = u;
    }
}

// ==================== direct bucket fill (no scan needed) ==================
__global__ void fill_kernel(const void* __restrict__ ei_raw, int E) {
    int e = blockIdx.x * blockDim.x + threadIdx.x;
    if (e >= E) return;
    int s, d;
    if (g_idx64) {
        const long long* ei = (const long long*)ei_raw;
        s = (int)ei[e]; d = (int)ei[E + e];
    } else {
        const int* ei = (const int*)ei_raw;
        s = ei[e]; d = ei[E + e];
    }
    int p1 = atomicAdd(&g_cnt_in[d], 1);
    if (p1 < CAP) {
        g_bkt_in[d * CAP + p1] = s;
    } else {
        int o = atomicAdd(&g_novf, 1);
        g_ovf_node[o] = d;            // dir 0
        g_ovf_nb[o]   = s;
    }
    int p2 = atomicAdd(&g_cnt_out[s], 1);
    if (p2 < CAP) {
        g_bkt_out[s * CAP + p2] = d;
    } else {
        int o = atomicAdd(&g_novf, 1);
        g_ovf_node[o] = s | (1 << 30);  // dir 1
        g_ovf_nb[o]   = d;
    }
}

// = gather-mean from fp16 mirror: grid-stride, 2 pairs/warp, prefetch, CAP=16
__global__ __launch_bounds__(256, 5)
void gather_kernel(int n) {
    const int lane  = threadIdx.x & 31;
    const int total = 2 * n;
    const int wstep = (gridDim.x * blockDim.x) >> 5;
    int wg = (blockIdx.x * blockDim.x + threadIdx.x) >> 5;
    if (wg >= total) return;

    const int co = lane * 4;   // 4 halfs per lane

    int pnode = wg >> 1, pdir = wg & 1;
    int pf_raw = 0;
    if (lane < CAP)
        pf_raw = (pdir ? &g_bkt_out[pnode * CAP] : &g_bkt_in[pnode * CAP])[lane];
    int pf_deg = pdir ? g_cnt_out[pnode] : g_cnt_in[pnode];

    for (; wg < total; wg += wstep) {
        const int node = wg >> 1, dir = wg & 1;
        int myid = pf_raw;
        int deg  = pf_deg;

        int wg2 = wg + wstep;
        if (wg2 < total) {
            int n2 = wg2 >> 1, d2 = wg2 & 1;
            pf_raw = 0;
            if (lane < CAP)
                pf_raw = (d2 ? &g_bkt_out[n2 * CAP] : &g_bkt_in[n2 * CAP])[lane];
            pf_deg = d2 ? g_cnt_out[n2] : g_cnt_in[n2];
        }

        int degc = deg < CAP ? deg : CAP;
        float4 a0 = make_float4(0.f, 0.f, 0.f, 0.f);
        float4 a1 = a0;

        int j = 0;
        for (; j + 4 <= degc; j += 4) {
            int n0 = __shfl_sync(0xFFFFFFFFu, myid, j);
            int n1 = __shfl_sync(0xFFFFFFFFu, myid, j + 1);
            int n2 = __shfl_sync(0xFFFFFFFFu, myid, j + 2);
            int n3 = __shfl_sync(0xFFFFFFFFu, myid, j + 3);
            uint2 u0 = __ldg((const uint2*)&g_xh[n0 * 128 + co]);
            uint2 u1 = __ldg((const uint2*)&g_xh[n1 * 128 + co]);
            uint2 u2 = __ldg((const uint2*)&g_xh[n2 * 128 + co]);
            uint2 u3 = __ldg((const uint2*)&g_xh[n3 * 128 + co]);
            float2 f;
            f = __half22float2(*(__half2*)&u0.x); a0.x += f.x; a0.y += f.y;
            f = __half22float2(*(__half2*)&u0.y); a0.z += f.x; a0.w += f.y;
            f = __half22float2(*(__half2*)&u1.x); a1.x += f.x; a1.y += f.y;
            f = __half22float2(*(__half2*)&u1.y); a1.z += f.x; a1.w += f.y;
            f = __half22float2(*(__half2*)&u2.x); a0.x += f.x; a0.y += f.y;
            f = __half22float2(*(__half2*)&u2.y); a0.z += f.x; a0.w += f.y;
            f = __half22float2(*(__half2*)&u3.x); a1.x += f.x; a1.y += f.y;
            f = __half22float2(*(__half2*)&u3.y); a1.z += f.x; a1.w += f.y;
        }
        for (; j < degc; j++) {
            int nb = __shfl_sync(0xFFFFFFFFu, myid, j);
            uint2 u = __ldg((const uint2*)&g_xh[nb * 128 + co]);
            float2 f;
            f = __half22float2(*(__half2*)&u.x); a0.x += f.x; a0.y += f.y;
            f = __half22float2(*(__half2*)&u.y); a0.z += f.x; a0.w += f.y;
        }

        float r = deg > 0 ? 1.f / (float)deg : 0.f;
        float4 s;
        s.x = (a0.x + a1.x) * r;
        s.y = (a0.y + a1.y) * r;
        s.z = (a0.z + a1.z) * r;
        s.w = (a0.w + a1.w) * r;
        float4* dst = dir ? g_agg_out : g_agg_in;
        dst[node * 32 + lane] = s;
    }
}

// ============ overflow fixup (grid-stride; ~1k records at CAP=16) ==========
__global__ void ovf_kernel(const float4* __restrict__ x4) {
    int novf = g_novf;
    int lane = threadIdx.x & 31;
    int wstep = (gridDim.x * blockDim.x) >> 5;
    for (int wrec = (blockIdx.x * blockDim.x + threadIdx.x) >> 5;
         wrec < novf; wrec += wstep) {
        int rec  = g_ovf_node[wrec];
        int dir  = (rec >> 30) & 1;
        int node = rec & 0x3FFFFFFF;
        int nb   = g_ovf_nb[wrec];
        int deg  = dir ? g_cnt_out[node] : g_cnt_in[node];
        float r  = 1.f / (float)deg;
        float4 v = __ldg(&x4[nb * 32 + lane]);
        v.x *= r; v.y *= r; v.z *= r; v.w *= r;
        float4* dst = dir ? g_agg_out : g_agg_in;
        red_add_f4(&dst[node * 32 + lane], v);
    }
}

// ============ fp16 A-split mma.sync GEMM (BM=128,BN=128,BK=32) =============
#define AOFF(buf, ksub, h) ((uint32_t)((((buf) * 2 + (ksub)) * 2 + (h)) * 6144))
#define BOFF(buf, ksub)    (49152u + (uint32_t)(((buf) * 2 + (ksub)) * 6144))
#define GEMM_SMEM (49152 + 4 * 6144)

__global__ __launch_bounds__(256, 2)
void gemm_kernel(const float4* __restrict__ x4,
                 const float* __restrict__ bself,
                 const float* __restrict__ bs2d,
                 const float* __restrict__ bd2s,
                 float* __restrict__ out, int n) {
    extern __shared__ char sm[];
    const uint32_t sb = smem_u32(sm);
    const int tid  = threadIdx.x;
    const int lane = tid & 31;
    const int wid  = tid >> 5;
    const int row0 = blockIdx.x * 128;
    const int wm = (wid >> 2) * 64;
    const int wn = (wid & 3) * 32;

    float acc[4][4][4];
#pragma unroll
    for (int i = 0; i < 4; i++)
#pragma unroll
        for (int j = 0; j < 4; j++)
#pragma unroll
            for (int q = 0; q < 4; q++) acc[i][j][q] = 0.f;

    const uint32_t arow = (uint32_t)((lane & 15) * 48 + ((lane >> 4) << 4));
    const uint32_t brow = (uint32_t)((lane & 7) * 48 + (((lane >> 3) & 1) << 4));

    const int arw  = tid >> 1;
    const int half = tid & 1;
    float4 pa[4];
    auto loadA = [&](int kc) {
        const int seg = kc >> 2;
        const float4* src = seg == 0 ? x4
                          : (seg == 1 ? (const float4*)g_agg_in
                                      : (const float4*)g_agg_out);
        const int r = row0 + arw;
        const int fb = (kc & 3) * 8 + half * 2;
#pragma unroll
        for (int ks = 0; ks < 2; ks++) {
#pragma unroll
            for (int j = 0; j < 2; j++) {
                pa[ks * 2 + j] = (r < n) ? src[r * 32 + fb + ks * 4 + j]
                                         : make_float4(0.f, 0.f, 0.f, 0.f);
            }
        }
    };
    auto storeA = [&](int buf) {
        const uint32_t doff = (uint32_t)(arw * 48 + half * 16);
#pragma unroll
        for (int ks = 0; ks < 2; ks++) {
            float4 f0 = pa[ks * 2], f1 = pa[ks * 2 + 1];
            float l0, l1, l2, l3, l4, l5, l6, l7;
            uint4 H, L;
            H.x = pack_hi2_f16(f0.x, f0.y, l0, l1);
            H.y = pack_hi2_f16(f0.z, f0.w, l2, l3);
            H.z = pack_hi2_f16(f1.x, f1.y, l4, l5);
            H.w = pack_hi2_f16(f1.z, f1.w, l6, l7);
            L.x = pack_f16x2(l0, l1); L.y = pack_f16x2(l2, l3);
            L.z = pack_f16x2(l4, l5); L.w = pack_f16x2(l6, l7);
            *(uint4*)(sm + AOFF(buf, ks, 0) + doff) = H;
            *(uint4*)(sm + AOFF(buf, ks, 1) + doff) = L;
        }
    };
    auto issueB = [&](int kc, int buf) {
        int ks = tid >> 7, nrow = tid & 127;
        const __half* src = &g_Wh[(2 * kc + ks) * 2048 + nrow * 16];
        uint32_t dst = sb + BOFF(buf, ks) + (uint32_t)(nrow * 48);
        cp_async16(dst, src);
        cp_async16(dst + 16, src + 8);
        cp_commit();
    };

    issueB(0, 0);
    loadA(0);

    for (int kc = 0; kc < 12; kc++) {
        const int buf = kc & 1;
        storeA(buf);
        cp_wait0();
        __syncthreads();
        if (kc < 11) {
            issueB(kc + 1, buf ^ 1);
            loadA(kc + 1);
        }
#pragma unroll
        for (int ks = 0; ks < 2; ks++) {
            uint32_t bh[4][2];
            const uint32_t bbase = sb + (uint32_t)(wn * 48) + brow;
#pragma unroll
            for (int nt = 0; nt < 4; nt++) {
                uint32_t rb = bbase + (uint32_t)(nt * 8 * 48);
                ldm_x2(rb + BOFF(buf, ks), bh[nt][0], bh[nt][1]);
            }
            const uint32_t abase = sb + (uint32_t)(wm * 48) + arow;
#pragma unroll
            for (int mt = 0; mt < 4; mt++) {
                uint32_t ah[4], al[4];
                uint32_t ra = abase + (uint32_t)(mt * 16 * 48);
                ldm_x4(ra + AOFF(buf, ks, 0), ah[0], ah[1], ah[2], ah[3]);
                ldm_x4(ra + AOFF(buf, ks, 1), al[0], al[1], al[2], al[3]);
#pragma unroll
                for (int nt = 0; nt < 4; nt++) {
                    mma_f16(acc[mt][nt], ah, bh[nt]);
                    mma_f16(acc[mt][nt], al, bh[nt]);
                }
            }
        }
    }

    // ---- epilogue: bias + store ----
    const int g  = lane >> 2;
    const int t2 = (lane & 3) * 2;
    float2 bias2[4];
#pragma unroll
    for (int nt = 0; nt < 4; nt++) {
        int c = wn + nt * 8 + t2;
        bias2[nt].x = bself[c]     + 0.5f * (bs2d[c]     + bd2s[c]);
        bias2[nt].y = bself[c + 1] + 0.5f * (bs2d[c + 1] + bd2s[c + 1]);
    }
#pragma unroll
    for (int mt = 0; mt < 4; mt++) {
        int r0 = row0 + wm + mt * 16 + g;
        int r1 = r0 + 8;
#pragma unroll
        for (int nt = 0; nt < 4; nt++) {
            int c = wn + nt * 8 + t2;
            if (r0 < n) {
                float2 v;
                v.x = acc[mt][nt][0] + bias2[nt].x;
                v.y = acc[mt][nt][1] + bias2[nt].y;
                *(float2*)&out[r0 * 128 + c] = v;
            }
            if (r1 < n) {
                float2 v;
                v.x = acc[mt][nt][2] + bias2[nt].x;
                v.y = acc[mt][nt][3] + bias2[nt].y;
                *(float2*)&out[r1 * 128 + c] = v;
            }
        }
    }
}

// ================================ launch ===================================
extern "C" void kernel_launch(void* const* d_in, const int* in_sizes, int n_in,
                              void* d_out, int out_size) {
    const float* x     = (const float*)d_in[0];
    const float* Wself = (const float*)d_in[1];
    const float* bself = (const float*)d_in[2];
    const float* Ws2d  = (const float*)d_in[3];
    const float* bs2d  = (const float*)d_in[4];
    const float* Wd2s  = (const float*)d_in[5];
    const float* bd2s  = (const float*)d_in[6];
    const void*  ei    = d_in[7];

    const int n = in_sizes[0] / 128;
    const int E = in_sizes[7] / 2;

    float* out = (float*)d_out;

    static int inited = 0;
    if (!inited) {
        cudaFuncSetAttribute(gemm_kernel,
                             cudaFuncAttributeMaxDynamicSharedMemorySize, GEMM_SMEM);
        inited = 1;
    }

    init_kernel<<<(n + 255) / 256, 256>>>((const long long*)ei,
                                          (const float4*)x,
                                          Wself, Ws2d, Wd2s, E, n);
    fill_kernel<<<(E + 255) / 256, 256>>>(ei, E);

    int gwarps = (2 * n + 1) / 2;
    gather_kernel<<<(gwarps + 7) / 8, 256>>>(n);
    ovf_kernel<<<256, 256>>>((const float4*)x);

    int gblocks = (n + 127) / 128;
    gemm_kernel<<<gblocks, 256, GEMM_SMEM>>>((const float4*)x,
                                             bself, bs2d, bd2s, out, n);
}